// round 3
// baseline (speedup 1.0000x reference)
#include <cuda_runtime.h>
#include <cuda_bf16.h>
#include <cstddef>
#include <cstdint>

#define SEQ   2048
#define BATCH 64
#define NIN   256
#define HID   256

#define RNN_BLOCKS  64                   // 32 clusters x 2 CTAs
#define PROJ_TILES_N 4                   // 256 / 64
#define PROJ_CHUNKS  1024                // 131072 / 128 m-rows; chunk = 2 steps
#define PROJ_BLOCKS  (PROJ_CHUNKS * PROJ_TILES_N)
#define TOTAL_BLOCKS (RNN_BLOCKS + PROJ_BLOCKS)

// Scratch
__device__ float g_xp[(size_t)SEQ * BATCH * HID];
__device__ int   g_done[PROJ_CHUNKS];

// ---------------------------------------------------------------------------
// helpers
// ---------------------------------------------------------------------------
__device__ __forceinline__ uint32_t smem_u32(const void* p) {
    uint32_t a;
    asm("{ .reg .u64 t; cvta.to.shared.u64 t, %1; cvt.u32.u64 %0, t; }"
        : "=r"(a) : "l"(p));
    return a;
}

#define FMA2(acc, a, b)                                             \
    asm("fma.rn.f32x2 %0, %1, %2, %3;"                              \
        : "=l"(acc) : "l"(a), "l"(b), "l"(acc))

__device__ __forceinline__ unsigned long long pack_dup(float x) {
    unsigned long long d;
    asm("mov.b64 %0, {%1, %1};" : "=l"(d) : "r"(__float_as_uint(x)));
    return d;
}
__device__ __forceinline__ float2 unpack2(unsigned long long v) {
    float2 r;
    asm("mov.b64 {%0, %1}, %2;" : "=f"(r.x), "=f"(r.y) : "l"(v));
    return r;
}

__device__ __forceinline__ void mbar_wait(uint32_t mbar, uint32_t parity) {
    asm volatile(
        "{\n\t"
        ".reg .pred P;\n"
        "$WL%=:\n\t"
        "mbarrier.try_wait.parity.acquire.cta.shared::cta.b64 P, [%0], %1, 0x989680;\n\t"
        "@!P bra $WL%=;\n\t"
        "}"
        :: "r"(mbar), "r"(parity) : "memory");
}

__device__ __forceinline__ int ld_acquire_gpu(const int* p) {
    int v;
    asm volatile("ld.acquire.gpu.b32 %0, [%1];" : "=r"(v) : "l"(p) : "memory");
    return v;
}

// ---------------------------------------------------------------------------
// reset kernel: zero proj-completion flags (runs before fused kernel each replay)
// ---------------------------------------------------------------------------
__global__ void reset_kernel() {
    for (int i = threadIdx.x; i < PROJ_CHUNKS; i += blockDim.x) g_done[i] = 0;
}

// ---------------------------------------------------------------------------
// Fused kernel.
//   blocks [0, 64): recurrence. Cluster of 2 CTAs handles TWO batch elements
//     (software-pipelined: DSMEM partial-exchange latency of one batch hides
//     under the other batch's compute). W_hh k-half lives in registers.
//   blocks [64, 4160): projection GEMM tiles (BM=128, BN=64, BK=32); n-tile
//     fastest so m-chunks (=2 timesteps) complete in ascending order; each
//     finished chunk bumps g_done[chunk] (release). The rnn gates its xp
//     prefetch on those flags (acquire poll by t0, amortized every 16 steps).
// ---------------------------------------------------------------------------
__global__ void __launch_bounds__(256, 1) __cluster_dims__(2, 1, 1)
fused_kernel(const float* __restrict__ X,
             const float* __restrict__ W_ih,
             const float* __restrict__ W_hh,
             const float* __restrict__ b_ih,
             const float* __restrict__ b_hh,
             float* __restrict__ out)
{
    __shared__ float sm_hbuf[2][2][256];   // [batch][dblbuf][row]
    __shared__ float sm_pbuf[2][2][256];   // [batch][dblbuf][row] peer partials
    __shared__ __align__(8) unsigned long long sm_mbar[4];  // [batch*2 + buf]
    __shared__ float sm_As[32][132];       // proj A tile [k][m]
    __shared__ float sm_Bs[32][68];        // proj B tile [k][n]

    const int tid = threadIdx.x;

    if (blockIdx.x >= RNN_BLOCKS) {
        // ===================== PROJECTION PATH =====================
        const int pb    = blockIdx.x - RNN_BLOCKS;
        const int chunk = pb >> 2;                 // m-chunk (slow)
        const int ntile = pb & 3;                  // n-tile  (fast)
        const int m0    = chunk * 128;
        const int n0    = ntile * 64;
        const int tx    = tid & 15;
        const int ty    = tid >> 4;

        unsigned long long acc2[4][4];
#pragma unroll
        for (int i = 0; i < 4; i++)
#pragma unroll
            for (int j = 0; j < 4; j++) acc2[i][j] = 0ULL;

        for (int kb = 0; kb < NIN; kb += 32) {
#pragma unroll
            for (int it = 0; it < 4; it++) {
                int idx = tid + it * 256;
                int r   = idx >> 3;
                int c4  = idx & 7;
                float4 v = *(const float4*)&X[(size_t)(m0 + r) * NIN + kb + c4 * 4];
                sm_As[c4 * 4 + 0][r] = v.x;
                sm_As[c4 * 4 + 1][r] = v.y;
                sm_As[c4 * 4 + 2][r] = v.z;
                sm_As[c4 * 4 + 3][r] = v.w;
            }
#pragma unroll
            for (int it = 0; it < 2; it++) {
                int idx = tid + it * 256;
                int r   = idx >> 3;
                int c4  = idx & 7;
                float4 v = *(const float4*)&W_ih[(size_t)(n0 + r) * NIN + kb + c4 * 4];
                sm_Bs[c4 * 4 + 0][r] = v.x;
                sm_Bs[c4 * 4 + 1][r] = v.y;
                sm_Bs[c4 * 4 + 2][r] = v.z;
                sm_Bs[c4 * 4 + 3][r] = v.w;
            }
            __syncthreads();
#pragma unroll
            for (int k = 0; k < 32; k++) {
                const ulonglong2* ap = (const ulonglong2*)&sm_As[k][ty * 8];
                ulonglong2 av0 = ap[0];
                ulonglong2 av1 = ap[1];
                float4 bv = *(const float4*)&sm_Bs[k][tx * 4];
                unsigned long long bd0 = pack_dup(bv.x);
                unsigned long long bd1 = pack_dup(bv.y);
                unsigned long long bd2 = pack_dup(bv.z);
                unsigned long long bd3 = pack_dup(bv.w);
                FMA2(acc2[0][0], av0.x, bd0); FMA2(acc2[0][1], av0.x, bd1);
                FMA2(acc2[0][2], av0.x, bd2); FMA2(acc2[0][3], av0.x, bd3);
                FMA2(acc2[1][0], av0.y, bd0); FMA2(acc2[1][1], av0.y, bd1);
                FMA2(acc2[1][2], av0.y, bd2); FMA2(acc2[1][3], av0.y, bd3);
                FMA2(acc2[2][0], av1.x, bd0); FMA2(acc2[2][1], av1.x, bd1);
                FMA2(acc2[2][2], av1.x, bd2); FMA2(acc2[2][3], av1.x, bd3);
                FMA2(acc2[3][0], av1.y, bd0); FMA2(acc2[3][1], av1.y, bd1);
                FMA2(acc2[3][2], av1.y, bd2); FMA2(acc2[3][3], av1.y, bd3);
            }
            __syncthreads();
        }

        const int nbase = n0 + tx * 4;
        float4 bias;
        bias.x = b_ih[nbase + 0] + b_hh[nbase + 0];
        bias.y = b_ih[nbase + 1] + b_hh[nbase + 1];
        bias.z = b_ih[nbase + 2] + b_hh[nbase + 2];
        bias.w = b_ih[nbase + 3] + b_hh[nbase + 3];
#pragma unroll
        for (int mi = 0; mi < 4; mi++) {
            float2 c0 = unpack2(acc2[mi][0]);
            float2 c1 = unpack2(acc2[mi][1]);
            float2 c2 = unpack2(acc2[mi][2]);
            float2 c3 = unpack2(acc2[mi][3]);
            int mA = m0 + ty * 8 + 2 * mi;
            float4 v0 = { c0.x + bias.x, c1.x + bias.y, c2.x + bias.z, c3.x + bias.w };
            float4 v1 = { c0.y + bias.x, c1.y + bias.y, c2.y + bias.z, c3.y + bias.w };
            *(float4*)&g_xp[(size_t)mA * HID + nbase]       = v0;
            *(float4*)&g_xp[(size_t)(mA + 1) * HID + nbase] = v1;
        }

        __syncthreads();
        if (tid == 0) {
            __threadfence();
            atomicAdd(&g_done[chunk], 1);
        }
        return;
    }

    // ===================== RECURRENCE PATH =====================
    const int      t    = tid;
    const uint32_t rank = blockIdx.x & 1;
    const int      cid  = blockIdx.x >> 1;
    const int      b0   = 2 * cid;
    const int      b1   = 2 * cid + 1;
    const int      k0   = rank << 7;

    unsigned long long w2[64];
    {
        const ulonglong2* wp = (const ulonglong2*)(W_hh + (size_t)t * HID + k0);
#pragma unroll
        for (int i = 0; i < 32; i++) {
            ulonglong2 v = wp[i];
            w2[2 * i]     = v.x;
            w2[2 * i + 1] = v.y;
        }
    }

    sm_hbuf[0][0][t] = 0.f;
    sm_hbuf[1][0][t] = 0.f;
    if (t == 0) {
#pragma unroll
        for (int i = 0; i < 4; i++)
            asm volatile("mbarrier.init.shared.b64 [%0], 1;"
                         :: "r"(smem_u32(&sm_mbar[i])) : "memory");
    }
    __syncthreads();
    asm volatile("barrier.cluster.arrive.aligned;" ::: "memory");
    asm volatile("barrier.cluster.wait.aligned;"   ::: "memory");

    const uint32_t peer     = rank ^ 1u;
    const uint32_t pbuf_loc = smem_u32(&sm_pbuf[0][0][0]);
    const uint32_t mbar_loc = smem_u32(&sm_mbar[0]);
    uint32_t pbuf_rem, mbar_rem;
    asm("mapa.shared::cluster.u32 %0, %1, %2;"
        : "=r"(pbuf_rem) : "r"(pbuf_loc), "r"(peer));
    asm("mapa.shared::cluster.u32 %0, %1, %2;"
        : "=r"(mbar_rem) : "r"(mbar_loc), "r"(peer));

    // initial flag gate: chunks 0..17 cover xp[0..35]
    int wm = 0;
    if (t == 0) {
        while (wm <= 17) {
            if (ld_acquire_gpu(&g_done[wm]) >= PROJ_TILES_N) wm++;
        }
    }
    __syncthreads();

    const float* xp_b0 = g_xp + (size_t)b0 * HID + t;
    const float* xp_b1 = g_xp + (size_t)b1 * HID + t;
    float xa0 = xp_b0[0];
    float xa1 = xp_b0[(size_t)1 * BATCH * HID];
    float xa2 = xp_b0[(size_t)2 * BATCH * HID];
    float xb0 = xp_b1[0];
    float xb1 = xp_b1[(size_t)1 * BATCH * HID];
    float xb2 = xp_b1[(size_t)2 * BATCH * HID];

    float* out0 = out + (size_t)b0 * HID + t;
    float* out1 = out + (size_t)b1 * HID + t;
    const bool own = ((uint32_t)(t >> 7) == rank);

#pragma unroll 1
    for (int s = 0; s < SEQ; s++) {
        const uint32_t bufsel = (uint32_t)(s & 1);
        const uint32_t parity = (uint32_t)((s >> 1) & 1);

        // -------- batch 0 dot + send --------
        const ulonglong2* hp = (const ulonglong2*)(&sm_hbuf[0][s & 1][0] + k0);
        unsigned long long a0 = 0ULL, a1 = 0ULL, a2 = 0ULL, a3 = 0ULL;
#pragma unroll
        for (int i = 0; i < 16; i++) {
            ulonglong2 h01 = hp[2 * i];
            ulonglong2 h23 = hp[2 * i + 1];
            FMA2(a0, w2[4 * i + 0], h01.x);
            FMA2(a1, w2[4 * i + 1], h01.y);
            FMA2(a2, w2[4 * i + 2], h23.x);
            FMA2(a3, w2[4 * i + 3], h23.y);
        }
        float2 f0 = unpack2(a0), f1 = unpack2(a1);
        float2 f2 = unpack2(a2), f3 = unpack2(a3);
        float mine0 = ((f0.x + f0.y) + (f1.x + f1.y))
                    + ((f2.x + f2.y) + (f3.x + f3.y));
        asm volatile(
            "st.async.shared::cluster.mbarrier::complete_tx::bytes.b32 "
            "[%0], %1, [%2];"
            :: "r"(pbuf_rem + (bufsel << 10) + ((uint32_t)t << 2)),
               "r"(__float_as_uint(mine0)),
               "r"(mbar_rem + bufsel * 8)
            : "memory");
        if (t == 0)
            asm volatile("mbarrier.arrive.expect_tx.shared.b64 _, [%0], 1024;"
                         :: "r"(mbar_loc + bufsel * 8) : "memory");

        // -------- batch 1 dot + send (covers batch 0 flight) --------
        const ulonglong2* hq = (const ulonglong2*)(&sm_hbuf[1][s & 1][0] + k0);
        unsigned long long c0 = 0ULL, c1 = 0ULL, c2 = 0ULL, c3 = 0ULL;
#pragma unroll
        for (int i = 0; i < 16; i++) {
            ulonglong2 h01 = hq[2 * i];
            ulonglong2 h23 = hq[2 * i + 1];
            FMA2(c0, w2[4 * i + 0], h01.x);
            FMA2(c1, w2[4 * i + 1], h01.y);
            FMA2(c2, w2[4 * i + 2], h23.x);
            FMA2(c3, w2[4 * i + 3], h23.y);
        }
        float2 g0 = unpack2(c0), g1 = unpack2(c1);
        float2 g2 = unpack2(c2), g3 = unpack2(c3);
        float mine1 = ((g0.x + g0.y) + (g1.x + g1.y))
                    + ((g2.x + g2.y) + (g3.x + g3.y));
        asm volatile(
            "st.async.shared::cluster.mbarrier::complete_tx::bytes.b32 "
            "[%0], %1, [%2];"
            :: "r"(pbuf_rem + 2048u + (bufsel << 10) + ((uint32_t)t << 2)),
               "r"(__float_as_uint(mine1)),
               "r"(mbar_rem + 16u + bufsel * 8)
            : "memory");
        if (t == 0)
            asm volatile("mbarrier.arrive.expect_tx.shared.b64 _, [%0], 1024;"
                         :: "r"(mbar_loc + 16u + bufsel * 8) : "memory");

        // -------- finish batch 0 --------
        mbar_wait(mbar_loc + bufsel * 8, parity);
        {
            float theirs = sm_pbuf[0][s & 1][t];
            float lo = rank ? theirs : mine0;
            float hi = rank ? mine0  : theirs;
            float hv = tanhf(xa0 + (lo + hi));
            if (own) {
                sm_hbuf[0][(s + 1) & 1][t] = hv;
                out0[(size_t)s * BATCH * HID] = hv;
            }
        }

        // prefetch xp[s+3] + periodic flag gate (covers batch 1 flight)
        float xan = 0.f, xbn = 0.f;
        if (s + 3 < SEQ) {
            xan = xp_b0[(size_t)(s + 3) * BATCH * HID];
            xbn = xp_b1[(size_t)(s + 3) * BATCH * HID];
        }
        if ((s & 15) == 0 && t == 0) {
            int need = (s + 35) >> 1;
            if (need > PROJ_CHUNKS - 1) need = PROJ_CHUNKS - 1;
            while (wm <= need) {
                if (ld_acquire_gpu(&g_done[wm]) >= PROJ_TILES_N) wm++;
            }
        }

        // -------- finish batch 1 --------
        mbar_wait(mbar_loc + 16u + bufsel * 8, parity);
        {
            float theirs = sm_pbuf[1][s & 1][t];
            float lo = rank ? theirs : mine1;
            float hi = rank ? mine1  : theirs;
            float hv = tanhf(xb0 + (lo + hi));
            if (own) {
                sm_hbuf[1][(s + 1) & 1][t] = hv;
                out1[(size_t)s * BATCH * HID] = hv;
            }
        }

        xa0 = xa1; xa1 = xa2; xa2 = xan;
        xb0 = xb1; xb1 = xb2; xb2 = xbn;
        __syncthreads();
    }

    asm volatile("barrier.cluster.arrive.aligned;" ::: "memory");
    asm volatile("barrier.cluster.wait.aligned;"   ::: "memory");
}

// ---------------------------------------------------------------------------
extern "C" void kernel_launch(void* const* d_in, const int* in_sizes, int n_in,
                              void* d_out, int out_size)
{
    const float* input = (const float*)d_in[0];
    const float* W_ih  = (const float*)d_in[1];
    const float* W_hh  = (const float*)d_in[2];
    const float* b_ih  = (const float*)d_in[3];
    const float* b_hh  = (const float*)d_in[4];
    float* out = (float*)d_out;

    reset_kernel<<<1, 256>>>();
    fused_kernel<<<TOTAL_BLOCKS, 256>>>(input, W_ih, W_hh, b_ih, b_hh, out);
}

// round 4
// speedup vs baseline: 1.0723x; 1.0723x over previous
#include <cuda_runtime.h>
#include <cuda_bf16.h>
#include <cstddef>
#include <cstdint>

#define SEQ   2048
#define BATCH 64
#define NIN   256
#define HID   256

#define RNN_BLOCKS   128                 // 32 clusters x 4 CTAs
#define PROJ_TILES_N 4                   // 256 / 64
#define PROJ_CHUNKS  1024                // 131072 / 128 m-rows; chunk = 2 steps
#define PROJ_BLOCKS  (PROJ_CHUNKS * PROJ_TILES_N)
#define TOTAL_BLOCKS (RNN_BLOCKS + PROJ_BLOCKS)   // 4224, multiple of 4

// Scratch
__device__ float g_xp[(size_t)SEQ * BATCH * HID];
__device__ int   g_done[PROJ_CHUNKS];

// ---------------------------------------------------------------------------
// helpers
// ---------------------------------------------------------------------------
__device__ __forceinline__ uint32_t smem_u32(const void* p) {
    uint32_t a;
    asm("{ .reg .u64 t; cvta.to.shared.u64 t, %1; cvt.u32.u64 %0, t; }"
        : "=r"(a) : "l"(p));
    return a;
}

#define FMA2(acc, a, b)                                             \
    asm("fma.rn.f32x2 %0, %1, %2, %3;"                              \
        : "=l"(acc) : "l"(a), "l"(b), "l"(acc))

__device__ __forceinline__ unsigned long long pack_dup(float x) {
    unsigned long long d;
    asm("mov.b64 %0, {%1, %1};" : "=l"(d) : "r"(__float_as_uint(x)));
    return d;
}
__device__ __forceinline__ float2 unpack2(unsigned long long v) {
    float2 r;
    asm("mov.b64 {%0, %1}, %2;" : "=f"(r.x), "=f"(r.y) : "l"(v));
    return r;
}

__device__ __forceinline__ void mbar_wait(uint32_t mbar, uint32_t parity) {
    asm volatile(
        "{\n\t"
        ".reg .pred P;\n"
        "$WL%=:\n\t"
        "mbarrier.try_wait.parity.acquire.cta.shared::cta.b64 P, [%0], %1, 0x989680;\n\t"
        "@!P bra $WL%=;\n\t"
        "}"
        :: "r"(mbar), "r"(parity) : "memory");
}

__device__ __forceinline__ int ld_acquire_gpu(const int* p) {
    int v;
    asm volatile("ld.acquire.gpu.b32 %0, [%1];" : "=r"(v) : "l"(p) : "memory");
    return v;
}

// fast tanh: 1 - 2/(e^{2x}+1).  MUFU.EX2 + MUFU.RCP based, ~1e-6 rel err,
// correct saturation at +/-inf.
__device__ __forceinline__ float ftanh(float x) {
    float e = __expf(2.f * x);
    return 1.f - __fdividef(2.f, e + 1.f);
}

// ---------------------------------------------------------------------------
// reset kernel: zero proj-completion flags (each graph replay)
// ---------------------------------------------------------------------------
__global__ void reset_kernel() {
    for (int i = threadIdx.x; i < PROJ_CHUNKS; i += blockDim.x) g_done[i] = 0;
}

// ---------------------------------------------------------------------------
// Fused kernel, cluster dims (4,1,1).
//   blocks [0,128): recurrence. 4-CTA cluster per 2 batch elements.
//     CTA rank q owns rows/k-quarter [64q, 64q+64). Thread t computes the
//     k-quarter partial for output row t (weights in regs), st.asyncs the 4B
//     partial to row-owner CTA (t>>6). Owner combines 4 partials (float4
//     read), tanh, stores h locally (h never broadcast). Warps 0-1 combine
//     batch0, warps 2-3 batch1, warps 4-7 skip to the barrier.
//   blocks [128,4224): projection tiles (as R3), chunk flags gate rnn xp.
// ---------------------------------------------------------------------------
__global__ void __launch_bounds__(256, 2) __cluster_dims__(4, 1, 1)
fused_kernel(const float* __restrict__ X,
             const float* __restrict__ W_ih,
             const float* __restrict__ W_hh,
             const float* __restrict__ b_ih,
             const float* __restrict__ b_hh,
             float* __restrict__ out)
{
    __shared__ float sm_h[2][2][64];          // [batch][buf][row]
    __shared__ float sm_p[2][2][64][4];       // [batch][buf][row][srcCTA]
    __shared__ __align__(8) unsigned long long sm_mbar[4]; // [batch*2+buf]
    __shared__ float sm_As[32][132];          // proj A tile [k][m]
    __shared__ float sm_Bs[32][68];           // proj B tile [k][n]

    const int tid = threadIdx.x;

    if (blockIdx.x >= RNN_BLOCKS) {
        // ===================== PROJECTION PATH =====================
        const int pb    = blockIdx.x - RNN_BLOCKS;
        const int chunk = pb >> 2;
        const int ntile = pb & 3;
        const int m0    = chunk * 128;
        const int n0    = ntile * 64;
        const int tx    = tid & 15;
        const int ty    = tid >> 4;

        unsigned long long acc2[4][4];
#pragma unroll
        for (int i = 0; i < 4; i++)
#pragma unroll
            for (int j = 0; j < 4; j++) acc2[i][j] = 0ULL;

        for (int kb = 0; kb < NIN; kb += 32) {
#pragma unroll
            for (int it = 0; it < 4; it++) {
                int idx = tid + it * 256;
                int r   = idx >> 3;
                int c4  = idx & 7;
                float4 v = *(const float4*)&X[(size_t)(m0 + r) * NIN + kb + c4 * 4];
                sm_As[c4 * 4 + 0][r] = v.x;
                sm_As[c4 * 4 + 1][r] = v.y;
                sm_As[c4 * 4 + 2][r] = v.z;
                sm_As[c4 * 4 + 3][r] = v.w;
            }
#pragma unroll
            for (int it = 0; it < 2; it++) {
                int idx = tid + it * 256;
                int r   = idx >> 3;
                int c4  = idx & 7;
                float4 v = *(const float4*)&W_ih[(size_t)(n0 + r) * NIN + kb + c4 * 4];
                sm_Bs[c4 * 4 + 0][r] = v.x;
                sm_Bs[c4 * 4 + 1][r] = v.y;
                sm_Bs[c4 * 4 + 2][r] = v.z;
                sm_Bs[c4 * 4 + 3][r] = v.w;
            }
            __syncthreads();
#pragma unroll
            for (int k = 0; k < 32; k++) {
                const ulonglong2* ap = (const ulonglong2*)&sm_As[k][ty * 8];
                ulonglong2 av0 = ap[0];
                ulonglong2 av1 = ap[1];
                float4 bv = *(const float4*)&sm_Bs[k][tx * 4];
                unsigned long long bd0 = pack_dup(bv.x);
                unsigned long long bd1 = pack_dup(bv.y);
                unsigned long long bd2 = pack_dup(bv.z);
                unsigned long long bd3 = pack_dup(bv.w);
                FMA2(acc2[0][0], av0.x, bd0); FMA2(acc2[0][1], av0.x, bd1);
                FMA2(acc2[0][2], av0.x, bd2); FMA2(acc2[0][3], av0.x, bd3);
                FMA2(acc2[1][0], av0.y, bd0); FMA2(acc2[1][1], av0.y, bd1);
                FMA2(acc2[1][2], av0.y, bd2); FMA2(acc2[1][3], av0.y, bd3);
                FMA2(acc2[2][0], av1.x, bd0); FMA2(acc2[2][1], av1.x, bd1);
                FMA2(acc2[2][2], av1.x, bd2); FMA2(acc2[2][3], av1.x, bd3);
                FMA2(acc2[3][0], av1.y, bd0); FMA2(acc2[3][1], av1.y, bd1);
                FMA2(acc2[3][2], av1.y, bd2); FMA2(acc2[3][3], av1.y, bd3);
            }
            __syncthreads();
        }

        const int nbase = n0 + tx * 4;
        float4 bias;
        bias.x = b_ih[nbase + 0] + b_hh[nbase + 0];
        bias.y = b_ih[nbase + 1] + b_hh[nbase + 1];
        bias.z = b_ih[nbase + 2] + b_hh[nbase + 2];
        bias.w = b_ih[nbase + 3] + b_hh[nbase + 3];
#pragma unroll
        for (int mi = 0; mi < 4; mi++) {
            float2 c0 = unpack2(acc2[mi][0]);
            float2 c1 = unpack2(acc2[mi][1]);
            float2 c2 = unpack2(acc2[mi][2]);
            float2 c3 = unpack2(acc2[mi][3]);
            int mA = m0 + ty * 8 + 2 * mi;
            float4 v0 = { c0.x + bias.x, c1.x + bias.y, c2.x + bias.z, c3.x + bias.w };
            float4 v1 = { c0.y + bias.x, c1.y + bias.y, c2.y + bias.z, c3.y + bias.w };
            *(float4*)&g_xp[(size_t)mA * HID + nbase]       = v0;
            *(float4*)&g_xp[(size_t)(mA + 1) * HID + nbase] = v1;
        }

        __syncthreads();
        if (tid == 0) {
            __threadfence();
            atomicAdd(&g_done[chunk], 1);
        }
        return;
    }

    // ===================== RECURRENCE PATH =====================
    const int t    = tid;
    const int warp = t >> 5;
    const int q    = blockIdx.x & 3;          // cluster rank = k-quarter
    const int cid  = blockIdx.x >> 2;
    const int b0   = 2 * cid;
    const int b1   = 2 * cid + 1;

    // weights: W_hh[row t][64q .. 64q+64) -> 32 u64 regs
    unsigned long long w2[32];
    {
        const ulonglong2* wp =
            (const ulonglong2*)(W_hh + (size_t)t * HID + q * 64);
#pragma unroll
        for (int i = 0; i < 16; i++) {
            ulonglong2 v = wp[i];
            w2[2 * i]     = v.x;
            w2[2 * i + 1] = v.y;
        }
    }

    if (t < 64) { sm_h[0][0][t] = 0.f; sm_h[1][0][t] = 0.f; }
    if (t == 0) {
#pragma unroll
        for (int i = 0; i < 4; i++)
            asm volatile("mbarrier.init.shared.b64 [%0], 1;"
                         :: "r"(smem_u32(&sm_mbar[i])) : "memory");
    }
    __syncthreads();
    asm volatile("barrier.cluster.arrive.aligned;" ::: "memory");
    asm volatile("barrier.cluster.wait.aligned;"   ::: "memory");

    // per-thread remote addresses: row t's owner CTA is t>>6
    const uint32_t owner = (uint32_t)(t >> 6);
    const uint32_t rowin = (uint32_t)(t & 63);
    const uint32_t p_loc = smem_u32(&sm_p[0][0][0][0]);
    const uint32_t m_loc = smem_u32(&sm_mbar[0]);
    uint32_t p_rem, m_rem;
    asm("mapa.shared::cluster.u32 %0, %1, %2;"
        : "=r"(p_rem) : "r"(p_loc), "r"(owner));
    asm("mapa.shared::cluster.u32 %0, %1, %2;"
        : "=r"(m_rem) : "r"(m_loc), "r"(owner));
    p_rem += rowin * 16u + (uint32_t)q * 4u;   // [row][src] slot

    // initial flag gate: chunks 0..17 cover xp[0..35]
    int wm = 0;
    if (t == 0) {
        while (wm <= 17) {
            if (ld_acquire_gpu(&g_done[wm]) >= PROJ_TILES_N) wm++;
        }
    }
    __syncthreads();

    // combine-role setup: warps 0-1 -> batch0 rows, warps 2-3 -> batch1 rows
    const bool comb  = (warp < 4);
    const int  cb    = warp >> 1;              // which batch I combine (if comb)
    const int  crow  = t & 63;                 // local row index
    const float* xptr = g_xp + (size_t)(cb ? b1 : b0) * HID + q * 64 + crow;
    float x0 = 0.f, x1 = 0.f, x2 = 0.f;
    if (comb) {
        x0 = xptr[0];
        x1 = xptr[(size_t)1 * BATCH * HID];
        x2 = xptr[(size_t)2 * BATCH * HID];
    }
    float* outp = out + (size_t)(cb ? b1 : b0) * HID + q * 64 + crow;

#pragma unroll 1
    for (int s = 0; s < SEQ; s++) {
        const uint32_t buf = (uint32_t)(s & 1);
        const uint32_t par = (uint32_t)((s >> 1) & 1);

        // ---- batch 0 dot: 32 FFMA2 over own k-quarter ----
        {
            const ulonglong2* hp = (const ulonglong2*)&sm_h[0][buf][0];
            unsigned long long a0 = 0ULL, a1 = 0ULL;
#pragma unroll
            for (int i = 0; i < 16; i++) {
                ulonglong2 hv = hp[i];
                FMA2(a0, w2[2 * i],     hv.x);
                FMA2(a1, w2[2 * i + 1], hv.y);
            }
            float2 f0 = unpack2(a0), f1 = unpack2(a1);
            float mine = (f0.x + f0.y) + (f1.x + f1.y);
            asm volatile(
                "st.async.shared::cluster.mbarrier::complete_tx::bytes.b32 "
                "[%0], %1, [%2];"
                :: "r"(p_rem + (buf << 10)),
                   "r"(__float_as_uint(mine)),
                   "r"(m_rem + buf * 8u)
                : "memory");
        }
        if (t == 0)
            asm volatile("mbarrier.arrive.expect_tx.shared.b64 _, [%0], 1024;"
                         :: "r"(m_loc + buf * 8u) : "memory");

        // ---- batch 1 dot ----
        {
            const ulonglong2* hp = (const ulonglong2*)&sm_h[1][buf][0];
            unsigned long long a0 = 0ULL, a1 = 0ULL;
#pragma unroll
            for (int i = 0; i < 16; i++) {
                ulonglong2 hv = hp[i];
                FMA2(a0, w2[2 * i],     hv.x);
                FMA2(a1, w2[2 * i + 1], hv.y);
            }
            float2 f0 = unpack2(a0), f1 = unpack2(a1);
            float mine = (f0.x + f0.y) + (f1.x + f1.y);
            asm volatile(
                "st.async.shared::cluster.mbarrier::complete_tx::bytes.b32 "
                "[%0], %1, [%2];"
                :: "r"(p_rem + 2048u + (buf << 10)),
                   "r"(__float_as_uint(mine)),
                   "r"(m_rem + 16u + buf * 8u)
                : "memory");
        }
        if (t == 0)
            asm volatile("mbarrier.arrive.expect_tx.shared.b64 _, [%0], 1024;"
                         :: "r"(m_loc + 16u + buf * 8u) : "memory");

        // ---- combine (warps 0-3 only; warps 4-7 go to the barrier) ----
        if (comb) {
            mbar_wait(m_loc + (uint32_t)cb * 16u + buf * 8u, par);
            float4 pv = *(const float4*)&sm_p[cb][buf][crow][0];
            float sum = (pv.x + pv.y) + (pv.z + pv.w);
            float hv  = ftanh(sum + x0);
            sm_h[cb][buf ^ 1u][crow] = hv;
            outp[(size_t)s * BATCH * HID] = hv;

            // xp window rotate + prefetch s+3
            x0 = x1; x1 = x2;
            x2 = (s + 3 < SEQ) ? xptr[(size_t)(s + 3) * BATCH * HID] : 0.f;
        }

        // periodic proj-flag gate (t0 only, every 16 steps)
        if ((s & 15) == 0 && t == 0) {
            int need = (s + 35) >> 1;
            if (need > PROJ_CHUNKS - 1) need = PROJ_CHUNKS - 1;
            while (wm <= need) {
                if (ld_acquire_gpu(&g_done[wm]) >= PROJ_TILES_N) wm++;
            }
        }

        __syncthreads();
    }

    asm volatile("barrier.cluster.arrive.aligned;" ::: "memory");
    asm volatile("barrier.cluster.wait.aligned;"   ::: "memory");
}

// ---------------------------------------------------------------------------
extern "C" void kernel_launch(void* const* d_in, const int* in_sizes, int n_in,
                              void* d_out, int out_size)
{
    const float* input = (const float*)d_in[0];
    const float* W_ih  = (const float*)d_in[1];
    const float* W_hh  = (const float*)d_in[2];
    const float* b_ih  = (const float*)d_in[3];
    const float* b_hh  = (const float*)d_in[4];
    float* out = (float*)d_out;

    reset_kernel<<<1, 256>>>();
    fused_kernel<<<TOTAL_BLOCKS, 256>>>(input, W_ih, W_hh, b_ih, b_hh, out);
}

// round 5
// speedup vs baseline: 1.1474x; 1.0700x over previous
#include <cuda_runtime.h>
#include <cuda_bf16.h>
#include <cstddef>
#include <cstdint>

#define SEQ   2048
#define BATCH 64
#define NIN   256
#define HID   256

// Scratch: x_proj[s][b][h]
__device__ float g_xp[(size_t)SEQ * BATCH * HID];

// ---------------------------------------------------------------------------
// helpers
// ---------------------------------------------------------------------------
__device__ __forceinline__ uint32_t smem_u32(const void* p) {
    uint32_t a;
    asm("{ .reg .u64 t; cvta.to.shared.u64 t, %1; cvt.u32.u64 %0, t; }"
        : "=r"(a) : "l"(p));
    return a;
}

#define FMA2(acc, a, b)                                             \
    asm("fma.rn.f32x2 %0, %1, %2, %3;"                              \
        : "=l"(acc) : "l"(a), "l"(b), "l"(acc))

__device__ __forceinline__ unsigned long long pack_dup(float x) {
    unsigned long long d;
    asm("mov.b64 %0, {%1, %1};" : "=l"(d) : "r"(__float_as_uint(x)));
    return d;
}
__device__ __forceinline__ float2 unpack2(unsigned long long v) {
    float2 r;
    asm("mov.b64 {%0, %1}, %2;" : "=f"(r.x), "=f"(r.y) : "l"(v));
    return r;
}

__device__ __forceinline__ void mbar_wait(uint32_t mbar, uint32_t parity) {
    asm volatile(
        "{\n\t"
        ".reg .pred P;\n"
        "$WL%=:\n\t"
        "mbarrier.try_wait.parity.acquire.cta.shared::cta.b64 P, [%0], %1, 0x989680;\n\t"
        "@!P bra $WL%=;\n\t"
        "}"
        :: "r"(mbar), "r"(parity) : "memory");
}

// fast tanh: 1 - 2/(e^{2x}+1), MUFU-based, ~1e-6 rel err, saturates correctly.
__device__ __forceinline__ float ftanh(float x) {
    float e = __expf(2.f * x);
    return 1.f - __fdividef(2.f, e + 1.f);
}

// ---------------------------------------------------------------------------
// Kernel 1: input projection GEMM (f32x2), identical to the proven R2 version.
//   g_xp[m][n] = sum_k X[m][k] * W_ih[n][k] + b_ih[n] + b_hh[n]
// ---------------------------------------------------------------------------
__global__ void __launch_bounds__(256) proj_kernel(
    const float* __restrict__ X,
    const float* __restrict__ W,
    const float* __restrict__ b_ih,
    const float* __restrict__ b_hh)
{
    constexpr int BM = 128, BN = 64, BK = 32;
    __shared__ float As[BK][BM + 4];
    __shared__ float Bs[BK][BN + 4];

    const int tid = threadIdx.x;
    const int m0  = blockIdx.x * BM;
    const int n0  = blockIdx.y * BN;
    const int tx  = tid & 15;
    const int ty  = tid >> 4;

    unsigned long long acc2[4][4];
#pragma unroll
    for (int i = 0; i < 4; i++)
#pragma unroll
        for (int j = 0; j < 4; j++) acc2[i][j] = 0ULL;

    for (int kb = 0; kb < NIN; kb += BK) {
#pragma unroll
        for (int it = 0; it < 4; it++) {
            int idx = tid + it * 256;
            int r   = idx >> 3;
            int c4  = idx & 7;
            float4 v = *(const float4*)&X[(size_t)(m0 + r) * NIN + kb + c4 * 4];
            As[c4 * 4 + 0][r] = v.x;
            As[c4 * 4 + 1][r] = v.y;
            As[c4 * 4 + 2][r] = v.z;
            As[c4 * 4 + 3][r] = v.w;
        }
#pragma unroll
        for (int it = 0; it < 2; it++) {
            int idx = tid + it * 256;
            int r   = idx >> 3;
            int c4  = idx & 7;
            float4 v = *(const float4*)&W[(size_t)(n0 + r) * NIN + kb + c4 * 4];
            Bs[c4 * 4 + 0][r] = v.x;
            Bs[c4 * 4 + 1][r] = v.y;
            Bs[c4 * 4 + 2][r] = v.z;
            Bs[c4 * 4 + 3][r] = v.w;
        }
        __syncthreads();

#pragma unroll
        for (int k = 0; k < BK; k++) {
            const ulonglong2* ap = (const ulonglong2*)&As[k][ty * 8];
            ulonglong2 av0 = ap[0];
            ulonglong2 av1 = ap[1];
            float4 bv = *(const float4*)&Bs[k][tx * 4];
            unsigned long long bd0 = pack_dup(bv.x);
            unsigned long long bd1 = pack_dup(bv.y);
            unsigned long long bd2 = pack_dup(bv.z);
            unsigned long long bd3 = pack_dup(bv.w);
            FMA2(acc2[0][0], av0.x, bd0); FMA2(acc2[0][1], av0.x, bd1);
            FMA2(acc2[0][2], av0.x, bd2); FMA2(acc2[0][3], av0.x, bd3);
            FMA2(acc2[1][0], av0.y, bd0); FMA2(acc2[1][1], av0.y, bd1);
            FMA2(acc2[1][2], av0.y, bd2); FMA2(acc2[1][3], av0.y, bd3);
            FMA2(acc2[2][0], av1.x, bd0); FMA2(acc2[2][1], av1.x, bd1);
            FMA2(acc2[2][2], av1.x, bd2); FMA2(acc2[2][3], av1.x, bd3);
            FMA2(acc2[3][0], av1.y, bd0); FMA2(acc2[3][1], av1.y, bd1);
            FMA2(acc2[3][2], av1.y, bd2); FMA2(acc2[3][3], av1.y, bd3);
        }
        __syncthreads();
    }

    const int nbase = n0 + tx * 4;
    float4 bias;
    bias.x = b_ih[nbase + 0] + b_hh[nbase + 0];
    bias.y = b_ih[nbase + 1] + b_hh[nbase + 1];
    bias.z = b_ih[nbase + 2] + b_hh[nbase + 2];
    bias.w = b_ih[nbase + 3] + b_hh[nbase + 3];
#pragma unroll
    for (int mi = 0; mi < 4; mi++) {
        float2 c0 = unpack2(acc2[mi][0]);
        float2 c1 = unpack2(acc2[mi][1]);
        float2 c2 = unpack2(acc2[mi][2]);
        float2 c3 = unpack2(acc2[mi][3]);
        int mA = m0 + ty * 8 + 2 * mi;
        float4 v0 = { c0.x + bias.x, c1.x + bias.y, c2.x + bias.z, c3.x + bias.w };
        float4 v1 = { c0.y + bias.x, c1.y + bias.y, c2.y + bias.z, c3.y + bias.w };
        *(float4*)&g_xp[(size_t)mA * HID + nbase]       = v0;
        *(float4*)&g_xp[(size_t)(mA + 1) * HID + nbase] = v1;
    }
}

// ---------------------------------------------------------------------------
// Kernel 2: recurrence. 64 clusters x 2 CTAs, one batch per cluster.
//   CTA rank r owns k-half [128r, 128r+128) AND h rows [128r, 128r+128)
//   (the k-half dot reads exactly the h rows this CTA combines -> h is
//   strictly CTA-local, never communicated).
//   Thread t: partial for row t over own k-half (64 u64 weight regs).
//     - row t in own half   -> STS to sm_ownp[t&127]
//     - row t in peer half  -> STS to sm_stage[s&1][t&127]
//   One cp.async.bulk (512B) ships the staged partials to the peer's
//   sm_pbuf[s&1] with a SINGLE mbarrier tx-accounting event (vs 128
//   per-message st.async updates in R2/R4 -- the suspected serializer).
//   Threads 0-127 combine: ownp[u] + pbuf[u] + xp -> tanh -> h, out.
// ---------------------------------------------------------------------------
__global__ void __launch_bounds__(256, 1) __cluster_dims__(2, 1, 1)
rnn3_kernel(const float* __restrict__ W_hh, float* __restrict__ out)
{
    __shared__ float sm_h[2][128];                       // local h half
    __shared__ __align__(16) float sm_pbuf[2][128];      // peer partials in
    __shared__ __align__(16) float sm_stage[2][128];     // partials out
    __shared__ float sm_ownp[128];                       // own-CTA partials
    __shared__ __align__(8) unsigned long long sm_mbar[2];

    const int      t    = threadIdx.x;
    const uint32_t rank = blockIdx.x & 1;
    const int      b    = blockIdx.x >> 1;
    const int      k0   = rank << 7;
    const int      u    = t & 127;
    const bool     isown = ((uint32_t)(t >> 7) == rank);

    // weights: W_hh[row t][k0 .. k0+127] -> 64 u64 regs
    unsigned long long w2[64];
    {
        const ulonglong2* wp = (const ulonglong2*)(W_hh + (size_t)t * HID + k0);
#pragma unroll
        for (int i = 0; i < 32; i++) {
            ulonglong2 v = wp[i];
            w2[2 * i]     = v.x;
            w2[2 * i + 1] = v.y;
        }
    }

    if (t < 128) { sm_h[0][t] = 0.f; sm_h[1][t] = 0.f; }
    if (t == 0) {
        asm volatile("mbarrier.init.shared.b64 [%0], 1;"
                     :: "r"(smem_u32(&sm_mbar[0])) : "memory");
        asm volatile("mbarrier.init.shared.b64 [%0], 1;"
                     :: "r"(smem_u32(&sm_mbar[1])) : "memory");
    }
    __syncthreads();
    asm volatile("barrier.cluster.arrive.aligned;" ::: "memory");
    asm volatile("barrier.cluster.wait.aligned;"   ::: "memory");

    const uint32_t peer      = rank ^ 1u;
    const uint32_t stage_loc = smem_u32(&sm_stage[0][0]);
    const uint32_t pbuf_loc  = smem_u32(&sm_pbuf[0][0]);
    const uint32_t mbar_loc  = smem_u32(&sm_mbar[0]);
    uint32_t pbuf_rem, mbar_rem;
    asm("mapa.shared::cluster.u32 %0, %1, %2;"
        : "=r"(pbuf_rem) : "r"(pbuf_loc), "r"(peer));
    asm("mapa.shared::cluster.u32 %0, %1, %2;"
        : "=r"(mbar_rem) : "r"(mbar_loc), "r"(peer));

    // combine-side setup (threads 0-127): global row = 128*rank + u
    const float* xptr = g_xp + (size_t)b * HID + k0 + u;
    float x0 = 0.f, x1 = 0.f, x2 = 0.f;
    if (t < 128) {
        x0 = xptr[0];
        x1 = xptr[(size_t)1 * BATCH * HID];
        x2 = xptr[(size_t)2 * BATCH * HID];
    }
    float* outp = out + (size_t)b * HID + k0 + u;

#pragma unroll 1
    for (int s = 0; s < SEQ; s++) {
        const uint32_t buf = (uint32_t)(s & 1);
        const uint32_t par = (uint32_t)((s >> 1) & 1);

        // ---- dot: 64 FFMA2 over own k-half (h is CTA-local) ----
        const ulonglong2* hp = (const ulonglong2*)&sm_h[buf][0];
        unsigned long long a0 = 0ULL, a1 = 0ULL, a2 = 0ULL, a3 = 0ULL;
#pragma unroll
        for (int i = 0; i < 16; i++) {
            ulonglong2 h01 = hp[2 * i];
            ulonglong2 h23 = hp[2 * i + 1];
            FMA2(a0, w2[4 * i + 0], h01.x);
            FMA2(a1, w2[4 * i + 1], h01.y);
            FMA2(a2, w2[4 * i + 2], h23.x);
            FMA2(a3, w2[4 * i + 3], h23.y);
        }
        float2 f0 = unpack2(a0), f1 = unpack2(a1);
        float2 f2 = unpack2(a2), f3 = unpack2(a3);
        float mine = ((f0.x + f0.y) + (f1.x + f1.y))
                   + ((f2.x + f2.y) + (f3.x + f3.y));

        if (isown) sm_ownp[u]       = mine;   // stays local
        else       sm_stage[buf][u] = mine;   // shipped to peer
        __syncthreads();

        // ---- one bulk message: 512B staged partials -> peer pbuf[buf] ----
        if (t == 0) {
            asm volatile("mbarrier.arrive.expect_tx.shared.b64 _, [%0], 512;"
                         :: "r"(mbar_loc + buf * 8u) : "memory");
            asm volatile("fence.proxy.async.shared::cta;" ::: "memory");
            asm volatile(
                "cp.async.bulk.shared::cluster.shared::cta.mbarrier::complete_tx::bytes "
                "[%0], [%1], %2, [%3];"
                :: "r"(pbuf_rem + (buf << 9)),
                   "r"(stage_loc + (buf << 9)),
                   "r"(512),
                   "r"(mbar_rem + buf * 8u)
                : "memory");
        }

        // ---- combine (threads 0-127) ----
        if (t < 128) {
            mbar_wait(mbar_loc + buf * 8u, par);
            float sum = sm_ownp[u] + sm_pbuf[buf][u];
            float hv  = ftanh(sum + x0);
            sm_h[buf ^ 1u][u] = hv;
            outp[(size_t)s * BATCH * HID] = hv;

            x0 = x1; x1 = x2;
            x2 = (s + 3 < SEQ) ? xptr[(size_t)(s + 3) * BATCH * HID] : 0.f;
        }
        __syncthreads();
    }

    asm volatile("barrier.cluster.arrive.aligned;" ::: "memory");
    asm volatile("barrier.cluster.wait.aligned;"   ::: "memory");
}

// ---------------------------------------------------------------------------
extern "C" void kernel_launch(void* const* d_in, const int* in_sizes, int n_in,
                              void* d_out, int out_size)
{
    const float* input = (const float*)d_in[0];   // [SEQ, BATCH, NIN]
    const float* W_ih  = (const float*)d_in[1];   // [HID, NIN]
    const float* W_hh  = (const float*)d_in[2];   // [HID, HID]
    const float* b_ih  = (const float*)d_in[3];   // [HID]
    const float* b_hh  = (const float*)d_in[4];   // [HID]
    float* out = (float*)d_out;                   // [SEQ*BATCH, HID]

    // 1) projection (full chip)
    dim3 pgrid((SEQ * BATCH) / 128, HID / 64);
    proj_kernel<<<pgrid, 256>>>(input, W_ih, b_ih, b_hh);

    // 2) recurrence: 64 clusters x 2 CTAs, one batch per cluster
    rnn3_kernel<<<BATCH * 2, 256>>>(W_hh, out);
}

// round 7
// speedup vs baseline: 1.3201x; 1.1505x over previous
#include <cuda_runtime.h>
#include <cuda_bf16.h>
#include <cstddef>
#include <cstdint>

#define SEQ   2048
#define BATCH 64
#define NIN   256
#define HID   256

// Scratch: x_proj[s][b][h]
__device__ float g_xp[(size_t)SEQ * BATCH * HID];

// ---------------------------------------------------------------------------
// helpers
// ---------------------------------------------------------------------------
__device__ __forceinline__ uint32_t smem_u32(const void* p) {
    uint32_t a;
    asm("{ .reg .u64 t; cvta.to.shared.u64 t, %1; cvt.u32.u64 %0, t; }"
        : "=r"(a) : "l"(p));
    return a;
}

#define FMA2(acc, a, b)                                             \
    asm("fma.rn.f32x2 %0, %1, %2, %3;"                              \
        : "=l"(acc) : "l"(a), "l"(b), "l"(acc))

__device__ __forceinline__ unsigned long long pack_dup(float x) {
    unsigned long long d;
    asm("mov.b64 %0, {%1, %1};" : "=l"(d) : "r"(__float_as_uint(x)));
    return d;
}
__device__ __forceinline__ float2 unpack2(unsigned long long v) {
    float2 r;
    asm("mov.b64 {%0, %1}, %2;" : "=f"(r.x), "=f"(r.y) : "l"(v));
    return r;
}

__device__ __forceinline__ void mbar_wait(uint32_t mbar, uint32_t parity) {
    asm volatile(
        "{\n\t"
        ".reg .pred P;\n"
        "$WL%=:\n\t"
        "mbarrier.try_wait.parity.acquire.cta.shared::cta.b64 P, [%0], %1, 0x989680;\n\t"
        "@!P bra $WL%=;\n\t"
        "}"
        :: "r"(mbar), "r"(parity) : "memory");
}

// fast tanh: 1 - 2/(e^{2x}+1), MUFU-based, ~1e-6 rel err, saturates correctly.
__device__ __forceinline__ float ftanh(float x) {
    float e = __expf(2.f * x);
    return 1.f - __fdividef(2.f, e + 1.f);
}

// ---------------------------------------------------------------------------
// Kernel 1: input projection GEMM (f32x2) — unchanged (R2-proven, ~370us).
// ---------------------------------------------------------------------------
__global__ void __launch_bounds__(256) proj_kernel(
    const float* __restrict__ X,
    const float* __restrict__ W,
    const float* __restrict__ b_ih,
    const float* __restrict__ b_hh)
{
    constexpr int BM = 128, BN = 64, BK = 32;
    __shared__ float As[BK][BM + 4];
    __shared__ float Bs[BK][BN + 4];

    const int tid = threadIdx.x;
    const int m0  = blockIdx.x * BM;
    const int n0  = blockIdx.y * BN;
    const int tx  = tid & 15;
    const int ty  = tid >> 4;

    unsigned long long acc2[4][4];
#pragma unroll
    for (int i = 0; i < 4; i++)
#pragma unroll
        for (int j = 0; j < 4; j++) acc2[i][j] = 0ULL;

    for (int kb = 0; kb < NIN; kb += BK) {
#pragma unroll
        for (int it = 0; it < 4; it++) {
            int idx = tid + it * 256;
            int r   = idx >> 3;
            int c4  = idx & 7;
            float4 v = *(const float4*)&X[(size_t)(m0 + r) * NIN + kb + c4 * 4];
            As[c4 * 4 + 0][r] = v.x;
            As[c4 * 4 + 1][r] = v.y;
            As[c4 * 4 + 2][r] = v.z;
            As[c4 * 4 + 3][r] = v.w;
        }
#pragma unroll
        for (int it = 0; it < 2; it++) {
            int idx = tid + it * 256;
            int r   = idx >> 3;
            int c4  = idx & 7;
            float4 v = *(const float4*)&W[(size_t)(n0 + r) * NIN + kb + c4 * 4];
            Bs[c4 * 4 + 0][r] = v.x;
            Bs[c4 * 4 + 1][r] = v.y;
            Bs[c4 * 4 + 2][r] = v.z;
            Bs[c4 * 4 + 3][r] = v.w;
        }
        __syncthreads();

#pragma unroll
        for (int k = 0; k < BK; k++) {
            const ulonglong2* ap = (const ulonglong2*)&As[k][ty * 8];
            ulonglong2 av0 = ap[0];
            ulonglong2 av1 = ap[1];
            float4 bv = *(const float4*)&Bs[k][tx * 4];
            unsigned long long bd0 = pack_dup(bv.x);
            unsigned long long bd1 = pack_dup(bv.y);
            unsigned long long bd2 = pack_dup(bv.z);
            unsigned long long bd3 = pack_dup(bv.w);
            FMA2(acc2[0][0], av0.x, bd0); FMA2(acc2[0][1], av0.x, bd1);
            FMA2(acc2[0][2], av0.x, bd2); FMA2(acc2[0][3], av0.x, bd3);
            FMA2(acc2[1][0], av0.y, bd0); FMA2(acc2[1][1], av0.y, bd1);
            FMA2(acc2[1][2], av0.y, bd2); FMA2(acc2[1][3], av0.y, bd3);
            FMA2(acc2[2][0], av1.x, bd0); FMA2(acc2[2][1], av1.x, bd1);
            FMA2(acc2[2][2], av1.x, bd2); FMA2(acc2[2][3], av1.x, bd3);
            FMA2(acc2[3][0], av1.y, bd0); FMA2(acc2[3][1], av1.y, bd1);
            FMA2(acc2[3][2], av1.y, bd2); FMA2(acc2[3][3], av1.y, bd3);
        }
        __syncthreads();
    }

    const int nbase = n0 + tx * 4;
    float4 bias;
    bias.x = b_ih[nbase + 0] + b_hh[nbase + 0];
    bias.y = b_ih[nbase + 1] + b_hh[nbase + 1];
    bias.z = b_ih[nbase + 2] + b_hh[nbase + 2];
    bias.w = b_ih[nbase + 3] + b_hh[nbase + 3];
#pragma unroll
    for (int mi = 0; mi < 4; mi++) {
        float2 c0 = unpack2(acc2[mi][0]);
        float2 c1 = unpack2(acc2[mi][1]);
        float2 c2 = unpack2(acc2[mi][2]);
        float2 c3 = unpack2(acc2[mi][3]);
        int mA = m0 + ty * 8 + 2 * mi;
        float4 v0 = { c0.x + bias.x, c1.x + bias.y, c2.x + bias.z, c3.x + bias.w };
        float4 v1 = { c0.y + bias.x, c1.y + bias.y, c2.y + bias.z, c3.y + bias.w };
        *(float4*)&g_xp[(size_t)mA * HID + nbase]       = v0;
        *(float4*)&g_xp[(size_t)(mA + 1) * HID + nbase] = v1;
    }
}

// ---------------------------------------------------------------------------
// Kernel 2: recurrence — h-exchange design (R6 with the dot loops FIXED:
//   each k-quarter chunk is 64 floats = 16 ulonglong2; R6 only consumed 8).
//   64 clusters x 2 CTAs, one batch per cluster. CTA rank r owns output rows
//   [128r,128r+128). Fresh h values are st.async'd to the peer right after
//   tanh, so the DSMEM flight overlaps the next step's local-half chunk.
//   Thread t (u=t&127, q=t>>7): row 128r+u over k-quarters
//   {128r+64q} (local h, no wait) then {128(1-r)+64q} (peer h, after wait).
//   Only 64 floats of FMA sit after the mbarrier arrival on any warp.
// ---------------------------------------------------------------------------
__global__ void __launch_bounds__(256, 1) __cluster_dims__(2, 1, 1)
rnn4_kernel(const float* __restrict__ W_hh, float* __restrict__ out)
{
    __shared__ float sm_h[2][256];        // full h; peer half arrives by st.async
    __shared__ float sm_ps[2][128];       // partials [q][u]
    __shared__ __align__(8) unsigned long long sm_mbar[2];

    const int      t    = threadIdx.x;
    const int      u    = t & 127;
    const int      q    = t >> 7;
    const uint32_t rank = blockIdx.x & 1;
    const int      b    = blockIdx.x >> 1;

    const int row      = (int)(rank << 7) + u;                 // output row
    const int kc_local = (int)(rank << 7) + (q << 6);          // own h quarter
    const int kc_peer  = (int)((rank ^ 1u) << 7) + (q << 6);   // peer h quarter

    // weights: W_hh[row][kc_local..+64) and [kc_peer..+64) -> 32+32 u64 regs
    unsigned long long wl[32], wp[32];
    {
        const ulonglong2* a = (const ulonglong2*)(W_hh + (size_t)row * HID + kc_local);
        const ulonglong2* c = (const ulonglong2*)(W_hh + (size_t)row * HID + kc_peer);
#pragma unroll
        for (int i = 0; i < 16; i++) {
            ulonglong2 v = a[i];
            wl[2 * i] = v.x; wl[2 * i + 1] = v.y;
            ulonglong2 w = c[i];
            wp[2 * i] = w.x; wp[2 * i + 1] = w.y;
        }
    }

    if (t == 0) {
        asm volatile("mbarrier.init.shared.b64 [%0], 1;"
                     :: "r"(smem_u32(&sm_mbar[0])) : "memory");
        asm volatile("mbarrier.init.shared.b64 [%0], 1;"
                     :: "r"(smem_u32(&sm_mbar[1])) : "memory");
    }
    if (t < 128) sm_h[0][(rank << 7) + t] = 0.f;   // local h half, buffer 0
    __syncthreads();
    asm volatile("barrier.cluster.arrive.aligned;" ::: "memory");
    asm volatile("barrier.cluster.wait.aligned;"   ::: "memory");

    // remote addresses: h[row] goes to the SAME offset in the peer's sm_h
    const uint32_t peer  = rank ^ 1u;
    const uint32_t h_loc = smem_u32(&sm_h[0][0]);
    const uint32_t m_loc = smem_u32(&sm_mbar[0]);
    uint32_t h_rem, m_rem;
    asm("mapa.shared::cluster.u32 %0, %1, %2;"
        : "=r"(h_rem) : "r"(h_loc), "r"(peer));
    asm("mapa.shared::cluster.u32 %0, %1, %2;"
        : "=r"(m_rem) : "r"(m_loc), "r"(peer));
    const uint32_t h_rem_row = h_rem + ((uint32_t)row << 2);   // + buf*1024

    // prologue: expect + send zero h_0 (uniform parity: bar[s&1], (s>>1)&1)
    if (t == 0)
        asm volatile("mbarrier.arrive.expect_tx.shared.b64 _, [%0], 512;"
                     :: "r"(m_loc) : "memory");
    if (t < 128)
        asm volatile(
            "st.async.shared::cluster.mbarrier::complete_tx::bytes.b32 "
            "[%0], %1, [%2];"
            :: "r"(h_rem_row), "r"(0u), "r"(m_rem) : "memory");

    // xp window (combine threads only)
    const float* xptr = g_xp + (size_t)b * HID + row;
    float x0 = 0.f, x1 = 0.f, x2 = 0.f;
    if (t < 128) {
        x0 = xptr[0];
        x1 = xptr[(size_t)1 * BATCH * HID];
        x2 = xptr[(size_t)2 * BATCH * HID];
    }
    float* outp = out + (size_t)b * HID + row;

#pragma unroll 1
    for (int s = 0; s < SEQ; s++) {
        const uint32_t buf = (uint32_t)(s & 1);
        const uint32_t nb  = buf ^ 1u;
        const uint32_t par = (uint32_t)((s >> 1) & 1);

        // expect tx for NEXT step's receive
        if (t == 0)
            asm volatile("mbarrier.arrive.expect_tx.shared.b64 _, [%0], 512;"
                         :: "r"(m_loc + nb * 8u) : "memory");

        // ---- local-half chunk: 64 floats (16 ulonglong2), no wait ----
        unsigned long long a0 = 0ULL, a1 = 0ULL;
        {
            const ulonglong2* hp = (const ulonglong2*)&sm_h[buf][kc_local];
#pragma unroll
            for (int i = 0; i < 16; i++) {
                ulonglong2 hv = hp[i];
                FMA2(a0, wl[2 * i],     hv.x);
                FMA2(a1, wl[2 * i + 1], hv.y);
            }
        }

        // ---- wait for peer h (flight overlapped the local chunk) ----
        mbar_wait(m_loc + buf * 8u, par);

        // ---- peer-half chunk: 64 floats (16 ulonglong2) ----
        {
            const ulonglong2* hp = (const ulonglong2*)&sm_h[buf][kc_peer];
#pragma unroll
            for (int i = 0; i < 16; i++) {
                ulonglong2 hv = hp[i];
                FMA2(a0, wp[2 * i],     hv.x);
                FMA2(a1, wp[2 * i + 1], hv.y);
            }
        }
        float2 f0 = unpack2(a0), f1 = unpack2(a1);
        sm_ps[q][u] = (f0.x + f0.y) + (f1.x + f1.y);
        __syncthreads();

        // ---- combine + tanh + publish (threads 0-127) ----
        if (t < 128) {
            float sum = sm_ps[0][u] + sm_ps[1][u];
            float hv  = ftanh(sum + x0);
            sm_h[nb][row] = hv;                       // local copy
            asm volatile(
                "st.async.shared::cluster.mbarrier::complete_tx::bytes.b32 "
                "[%0], %1, [%2];"
                :: "r"(h_rem_row + (nb << 10)),
                   "r"(__float_as_uint(hv)),
                   "r"(m_rem + nb * 8u)
                : "memory");
            outp[(size_t)s * BATCH * HID] = hv;

            x0 = x1; x1 = x2;
            x2 = (s + 3 < SEQ) ? xptr[(size_t)(s + 3) * BATCH * HID] : 0.f;
        }
        __syncthreads();   // sm_h[nb] local half visible for next local chunk
    }

    asm volatile("barrier.cluster.arrive.aligned;" ::: "memory");
    asm volatile("barrier.cluster.wait.aligned;"   ::: "memory");
}

// ---------------------------------------------------------------------------
extern "C" void kernel_launch(void* const* d_in, const int* in_sizes, int n_in,
                              void* d_out, int out_size)
{
    const float* input = (const float*)d_in[0];   // [SEQ, BATCH, NIN]
    const float* W_ih  = (const float*)d_in[1];   // [HID, NIN]
    const float* W_hh  = (const float*)d_in[2];   // [HID, HID]
    const float* b_ih  = (const float*)d_in[3];   // [HID]
    const float* b_hh  = (const float*)d_in[4];   // [HID]
    float* out = (float*)d_out;                   // [SEQ*BATCH, HID]

    // 1) projection (full chip)
    dim3 pgrid((SEQ * BATCH) / 128, HID / 64);
    proj_kernel<<<pgrid, 256>>>(input, W_ih, b_ih, b_hh);

    // 2) recurrence: 64 clusters x 2 CTAs, one batch per cluster
    rnn4_kernel<<<BATCH * 2, 256>>>(W_hh, out);
}